// round 14
// baseline (speedup 1.0000x reference)
#include <cuda_runtime.h>
#include <cuda_fp16.h>
#include <cstdint>
#include <math.h>

// Problem dims
#define B_ROWS 16384
#define IN_DIM 2048
#define OUT_DIM 2048

// GEMM tiling: CTA 128x128, 4 warps (2x2), warp tile 64x64, K-chunk 32, 4 stages
#define TM 128
#define TN 128
#define KC 32
#define KSTEPS (IN_DIM / KC)   // 64
#define STAGES 4

#define ROW_STRIDE 80                     // 32 fp16 = 64B, padded to 80B (conflict-free ldmatrix)
#define A_STAGE_BYTES (TM * ROW_STRIDE)   // 10240
#define B_STAGE_BYTES (TN * ROW_STRIDE)   // 10240
#define SMEM_A 0
#define SMEM_B (STAGES * A_STAGE_BYTES)   // 40960
#define SMEM_TOTAL (SMEM_B + STAGES * B_STAGE_BYTES)  // 81920 (2 CTAs/SM)

// Named barriers: VIS[s] = id s (fill of slot s visible), OVW[s] = id 4+s (slot s consumed)
#define BAR_CNT 256   // 128 arrives + 128 syncs

// Scratch (static device arrays are allowed)
__device__ __half g_x16[(size_t)B_ROWS * IN_DIM];   // 64 MiB: normalized x, fp16
__device__ __half g_w16[(size_t)OUT_DIM * IN_DIM];  // 8 MiB:  W, fp16

// ---------------------------------------------------------------------------
// PTX helpers (baseline PTX only)
// ---------------------------------------------------------------------------
__device__ __forceinline__ uint32_t smem_to_u32(const void* smem_ptr) {
    uint32_t addr;
    asm("{ .reg .u64 tmp; cvta.to.shared.u64 tmp, %1; cvt.u32.u64 %0, tmp; }"
        : "=r"(addr) : "l"(smem_ptr));
    return addr;
}

__device__ __forceinline__ void cp16(uint32_t smem_addr, const void* gptr) {
    asm volatile("cp.async.cg.shared.global [%0], [%1], 16;"
                 :: "r"(smem_addr), "l"(gptr));
}

__device__ __forceinline__ void ldsm_x4(uint32_t* r, uint32_t addr) {
    asm volatile("ldmatrix.sync.aligned.m8n8.x4.shared.b16 {%0,%1,%2,%3}, [%4];"
                 : "=r"(r[0]), "=r"(r[1]), "=r"(r[2]), "=r"(r[3]) : "r"(addr));
}

__device__ __forceinline__ void mma16816(float* c, const uint32_t* a, const uint32_t* b) {
    asm volatile(
        "mma.sync.aligned.m16n8k16.row.col.f32.f16.f16.f32 "
        "{%0,%1,%2,%3}, {%4,%5,%6,%7}, {%8,%9}, {%0,%1,%2,%3};"
        : "+f"(c[0]), "+f"(c[1]), "+f"(c[2]), "+f"(c[3])
        : "r"(a[0]), "r"(a[1]), "r"(a[2]), "r"(a[3]), "r"(b[0]), "r"(b[1]));
}

__device__ __forceinline__ void bar_sync_n(int id) {
    asm volatile("bar.sync %0, %1;" :: "r"(id), "n"(BAR_CNT) : "memory");
}
__device__ __forceinline__ void bar_arrive_n(int id) {
    asm volatile("bar.arrive %0, %1;" :: "r"(id), "n"(BAR_CNT) : "memory");
}

// ---------------------------------------------------------------------------
// Kernel 1 (fused prep): blocks [0,16384) normalize x rows -> fp16;
//                        blocks [16384,18432) convert W -> fp16.
// ---------------------------------------------------------------------------
__global__ void __launch_bounds__(256) prep_kernel(const float* __restrict__ x,
                                                   const float* __restrict__ W) {
    const int tid = threadIdx.x;
    if (blockIdx.x >= B_ROWS) {
        const size_t idx = ((size_t)(blockIdx.x - B_ROWS) * 256 + tid) * 8;
        float4 a = *reinterpret_cast<const float4*>(W + idx);
        float4 b = *reinterpret_cast<const float4*>(W + idx + 4);
        __half2 h[4];
        h[0] = __floats2half2_rn(a.x, a.y);
        h[1] = __floats2half2_rn(a.z, a.w);
        h[2] = __floats2half2_rn(b.x, b.y);
        h[3] = __floats2half2_rn(b.z, b.w);
        *reinterpret_cast<uint4*>(&g_w16[idx]) = *reinterpret_cast<uint4*>(h);
        return;
    }
    const int row = blockIdx.x;
    const float4* xr = reinterpret_cast<const float4*>(x + (size_t)row * IN_DIM);
    float4 a = xr[tid * 2];
    float4 b = xr[tid * 2 + 1];
    float s = a.x * a.x + a.y * a.y + a.z * a.z + a.w * a.w
            + b.x * b.x + b.y * b.y + b.z * b.z + b.w * b.w;
    #pragma unroll
    for (int off = 16; off; off >>= 1) s += __shfl_xor_sync(0xffffffffu, s, off);
    __shared__ float warpsum[8];
    const int warp = tid >> 5, lane = tid & 31;
    if (lane == 0) warpsum[warp] = s;
    __syncthreads();
    if (tid == 0) {
        float t = 0.0f;
        #pragma unroll
        for (int i = 0; i < 8; ++i) t += warpsum[i];
        warpsum[0] = 1.0f / (sqrtf(t) + 1e-4f);
    }
    __syncthreads();
    const float inv = warpsum[0];
    __half2 h[4];
    h[0] = __floats2half2_rn(a.x * inv, a.y * inv);
    h[1] = __floats2half2_rn(a.z * inv, a.w * inv);
    h[2] = __floats2half2_rn(b.x * inv, b.y * inv);
    h[3] = __floats2half2_rn(b.z * inv, b.w * inv);
    *reinterpret_cast<uint4*>(&g_x16[(size_t)row * IN_DIM + tid * 8]) =
        *reinterpret_cast<uint4*>(h);
}

// ---------------------------------------------------------------------------
// Kernel 2: HMMA GEMM with warp-asynchronous pipeline (named barriers,
// one-kiter slack on both fill-visibility and overwrite hazards).
// ---------------------------------------------------------------------------
__global__ void __launch_bounds__(128, 2)
gemm_kernel(const float* __restrict__ bias, float* __restrict__ out) {
    extern __shared__ __align__(128) char smem[];
    const uint32_t smem_base = smem_to_u32(smem);
    const int tid = threadIdx.x;
    const int wid = tid >> 5;
    const int lane = tid & 31;
    const int warp_m = wid & 1;     // 2 x 2 warp grid, warp tile 64x64
    const int warp_n = wid >> 1;

    const int n_tile = blockIdx.x;  // fast axis -> W stays L2-resident
    const int m_tile = blockIdx.y;
    const int m_base = m_tile * TM;
    const int n_base = n_tile * TN;

    const __half* Ag = g_x16 + (size_t)m_base * IN_DIM;
    const __half* Bg = g_w16 + (size_t)n_base * IN_DIM;

    // per-thread fill offsets
    const uint32_t smF = (uint32_t)((tid >> 2) * ROW_STRIDE + (tid & 3) * 16);
    const size_t gF = (size_t)(tid >> 2) * IN_DIM + (tid & 3) * 8;

    // fill: 4 A rows + 4 B rows per thread, static strides
    auto fill = [&](int slot, int kk) {
        const uint32_t a_s = smem_base + SMEM_A + slot * A_STAGE_BYTES + smF;
        const uint32_t b_s = smem_base + SMEM_B + slot * B_STAGE_BYTES + smF;
        const __half* Af = Ag + gF + kk;
        const __half* Bf = Bg + gF + kk;
        #pragma unroll
        for (int j = 0; j < 4; ++j)
            cp16(a_s + j * (32 * ROW_STRIDE), Af + (size_t)j * (32 * IN_DIM));
        #pragma unroll
        for (int j = 0; j < 4; ++j)
            cp16(b_s + j * (32 * ROW_STRIDE), Bf + (size_t)j * (32 * IN_DIM));
    };

    float c[4][8][4];
    #pragma unroll
    for (int mt = 0; mt < 4; ++mt)
        #pragma unroll
        for (int nt = 0; nt < 8; ++nt)
            #pragma unroll
            for (int i = 0; i < 4; ++i) c[mt][nt][i] = 0.0f;

    // ldmatrix per-thread offsets
    const uint32_t a_off =
        (uint32_t)((warp_m * 64 + (lane & 15)) * ROW_STRIDE + ((lane >> 4) << 4)) + SMEM_A;
    const uint32_t b_off =
        (uint32_t)((warp_n * 64 + ((lane >> 4) << 3) + (lane & 7)) * ROW_STRIDE
                   + ((lane & 8) << 1)) + SMEM_B;

    // one full kiter: sync VIS[slot]; LDSM both k16 steps; arrive OVW[slot];
    // optional fill of slot (slot+3)&3 (guarded by OVW sync); commit; wait;
    // optional arrive VIS[(slot+1)&3]; MMA trains.
    auto kiter = [&](int slot, int fill_kk, bool do_fill, bool do_vis_arrive) {
        bar_sync_n(slot);                       // fills of this slot visible
        const uint32_t a_base = smem_base + slot * A_STAGE_BYTES + a_off;
        const uint32_t b_base = smem_base + slot * B_STAGE_BYTES + b_off;
        uint32_t a[2][4][4];
        uint32_t b[2][4][4];
        #pragma unroll
        for (int s = 0; s < 2; ++s) {
            #pragma unroll
            for (int mt = 0; mt < 4; ++mt)
                ldsm_x4(a[s][mt], a_base + mt * (16 * ROW_STRIDE) + s * 32);
            #pragma unroll
            for (int nt2 = 0; nt2 < 4; ++nt2)
                ldsm_x4(b[s][nt2], b_base + nt2 * (16 * ROW_STRIDE) + s * 32);
        }
        bar_arrive_n(4 + slot);                 // this slot fully consumed
        if (do_fill) {
            const int fslot = (slot + 3) & 3;
            bar_sync_n(4 + fslot);              // prior consumers of fslot done
            fill(fslot, fill_kk);
        }
        asm volatile("cp.async.commit_group;" ::: "memory");
        asm volatile("cp.async.wait_group %0;" :: "n"(STAGES - 2) : "memory");
        if (do_vis_arrive)
            bar_arrive_n((slot + 1) & 3);       // own fill of next slot complete
        #pragma unroll
        for (int s = 0; s < 2; ++s)
            #pragma unroll
            for (int mt = 0; mt < 4; ++mt)
                #pragma unroll
                for (int nt = 0; nt < 8; ++nt)
                    mma16816(c[mt][nt], a[s][mt], &b[s][nt >> 1][(nt & 1) * 2]);
    };

    // Prologue: fill slots 0..2 (kiters 0..2), one commit group each
    #pragma unroll
    for (int s = 0; s < STAGES - 1; ++s) {
        fill(s, s * KC);
        asm volatile("cp.async.commit_group;" ::: "memory");
    }
    bar_arrive_n(4 + 3);                        // OVW[3]: slot 3 free initially
    asm volatile("cp.async.wait_group %0;" :: "n"(STAGES - 2) : "memory");
    bar_arrive_n(0);                            // VIS[0]: own fill of slot 0 done

    // kiters 0..59: always fill (kiter u+3), always VIS-arrive
    for (int kb = 0; kb < 15; ++kb) {
        const int kk0 = kb * 4 * KC;
        #pragma unroll
        for (int u4 = 0; u4 < 4; ++u4)
            kiter(u4, kk0 + (u4 + 3) * KC, true, true);
    }
    // tail kiters 60..63
    kiter(0, 63 * KC, true, true);    // u=60: fill kiter 63
    kiter(1, 0, false, true);         // u=61
    kiter(2, 0, false, true);         // u=62
    kiter(3, 0, false, false);        // u=63

    // Epilogue: bias + ReLU, fp32 stores (8B pairs)
    const int row0 = m_base + warp_m * 64 + (lane >> 2);
    const int col0 = n_base + warp_n * 64 + 2 * (lane & 3);
    float2 bv[8];
    #pragma unroll
    for (int nt = 0; nt < 8; ++nt)
        bv[nt] = *reinterpret_cast<const float2*>(&bias[col0 + nt * 8]);

    #pragma unroll
    for (int mt = 0; mt < 4; ++mt) {
        const size_t r0 = (size_t)(row0 + mt * 16) * OUT_DIM;
        const size_t r1 = r0 + 8 * OUT_DIM;
        #pragma unroll
        for (int nt = 0; nt < 8; ++nt) {
            const int cc = col0 + nt * 8;
            float2 v0, v1;
            v0.x = fmaxf(c[mt][nt][0] + bv[nt].x, 0.0f);
            v0.y = fmaxf(c[mt][nt][1] + bv[nt].y, 0.0f);
            v1.x = fmaxf(c[mt][nt][2] + bv[nt].x, 0.0f);
            v1.y = fmaxf(c[mt][nt][3] + bv[nt].y, 0.0f);
            *reinterpret_cast<float2*>(out + r0 + cc) = v0;
            *reinterpret_cast<float2*>(out + r1 + cc) = v1;
        }
    }
}

// ---------------------------------------------------------------------------
// Launch
// ---------------------------------------------------------------------------
extern "C" void kernel_launch(void* const* d_in, const int* in_sizes, int n_in,
                              void* d_out, int out_size) {
    const float* x = (const float*)d_in[0];
    const float* W = (const float*)d_in[1];
    const float* b = (const float*)d_in[2];
    float* out = (float*)d_out;

    cudaFuncSetAttribute(gemm_kernel, cudaFuncAttributeMaxDynamicSharedMemorySize,
                         SMEM_TOTAL);

    prep_kernel<<<B_ROWS + (OUT_DIM * IN_DIM) / (256 * 8), 256>>>(x, W);

    dim3 grid(OUT_DIM / TN, B_ROWS / TM);   // (16, 128), n-tile fastest
    gemm_kernel<<<grid, 128, SMEM_TOTAL>>>(b, out);
}

// round 16
// speedup vs baseline: 1.1023x; 1.1023x over previous
#include <cuda_runtime.h>
#include <cuda_fp16.h>
#include <cstdint>
#include <math.h>

// Problem dims
#define B_ROWS 16384
#define IN_DIM 2048
#define OUT_DIM 2048

// GEMM tiling: CTA 128x128, 4 warps (2x2), warp tile 64x64, K-chunk 32, 4 stages
#define TM 128
#define TN 128
#define KC 32
#define KSTEPS (IN_DIM / KC)   // 64
#define STAGES 4

#define ROW_STRIDE 80                     // 32 fp16 = 64B, padded to 80B (conflict-free ldmatrix)
#define A_STAGE_BYTES (TM * ROW_STRIDE)   // 10240
#define B_STAGE_BYTES (TN * ROW_STRIDE)   // 10240
#define SMEM_A 0
#define SMEM_B (STAGES * A_STAGE_BYTES)   // 40960
#define SMEM_TOTAL (SMEM_B + STAGES * B_STAGE_BYTES)  // 81920 (2 CTAs/SM)

// Scratch (static device arrays are allowed)
__device__ __half g_x16[(size_t)B_ROWS * IN_DIM];   // 64 MiB: normalized x, fp16
__device__ __half g_w16[(size_t)OUT_DIM * IN_DIM];  // 8 MiB:  W, fp16
__device__ int    g_cnt[B_ROWS / TM];               // per-m_tile producer counters

// ---------------------------------------------------------------------------
// PTX helpers (baseline PTX only)
// ---------------------------------------------------------------------------
__device__ __forceinline__ uint32_t smem_to_u32(const void* smem_ptr) {
    uint32_t addr;
    asm("{ .reg .u64 tmp; cvta.to.shared.u64 tmp, %1; cvt.u32.u64 %0, tmp; }"
        : "=r"(addr) : "l"(smem_ptr));
    return addr;
}

__device__ __forceinline__ void cp16(uint32_t smem_addr, const void* gptr) {
    asm volatile("cp.async.cg.shared.global [%0], [%1], 16;"
                 :: "r"(smem_addr), "l"(gptr));
}

__device__ __forceinline__ void ldsm_x4(uint32_t* r, uint32_t addr) {
    asm volatile("ldmatrix.sync.aligned.m8n8.x4.shared.b16 {%0,%1,%2,%3}, [%4];"
                 : "=r"(r[0]), "=r"(r[1]), "=r"(r[2]), "=r"(r[3]) : "r"(addr));
}

__device__ __forceinline__ void mma16816(float* c, const uint32_t* a, const uint32_t* b) {
    asm volatile(
        "mma.sync.aligned.m16n8k16.row.col.f32.f16.f16.f32 "
        "{%0,%1,%2,%3}, {%4,%5,%6,%7}, {%8,%9}, {%0,%1,%2,%3};"
        : "+f"(c[0]), "+f"(c[1]), "+f"(c[2]), "+f"(c[3])
        : "r"(a[0]), "r"(a[1]), "r"(a[2]), "r"(a[3]), "r"(b[0]), "r"(b[1]));
}

// ---------------------------------------------------------------------------
// Kernel 1: W fp32 -> fp16  +  zero the per-m_tile counters (each replay)
// ---------------------------------------------------------------------------
__global__ void __launch_bounds__(256) prep_w_kernel(const float* __restrict__ W) {
    const size_t idx = ((size_t)blockIdx.x * 256 + threadIdx.x) * 8;
    float4 a = *reinterpret_cast<const float4*>(W + idx);
    float4 b = *reinterpret_cast<const float4*>(W + idx + 4);
    __half2 h[4];
    h[0] = __floats2half2_rn(a.x, a.y);
    h[1] = __floats2half2_rn(a.z, a.w);
    h[2] = __floats2half2_rn(b.x, b.y);
    h[3] = __floats2half2_rn(b.z, b.w);
    *reinterpret_cast<uint4*>(&g_w16[idx]) = *reinterpret_cast<uint4*>(h);
    if (blockIdx.x == 0 && threadIdx.x < B_ROWS / TM)
        g_cnt[threadIdx.x] = 0;
}

// ---------------------------------------------------------------------------
// Kernel 2: fused x-prep producer/consumer + HMMA GEMM (R2 core, unchanged).
// CTA (m,n) first normalizes+converts x rows [m*128 + n*8, +8), signals
// cnt[m]; then waits for cnt[m]==16 and runs the GEMM tile.
// ---------------------------------------------------------------------------
__global__ void __launch_bounds__(128, 2)
gemm_kernel(const float* __restrict__ x, const float* __restrict__ bias,
            float* __restrict__ out) {
    extern __shared__ __align__(128) char smem[];
    const uint32_t smem_base = smem_to_u32(smem);
    const int tid = threadIdx.x;
    const int wid = tid >> 5;
    const int lane = tid & 31;
    const int warp_m = wid & 1;     // 2 x 2 warp grid, warp tile 64x64
    const int warp_n = wid >> 1;

    const int n_tile = blockIdx.x;  // fast axis -> W stays L2-resident
    const int m_tile = blockIdx.y;
    const int m_base = m_tile * TM;
    const int n_base = n_tile * TN;

    // ---- Phase 0: produce 8 x rows (2 per warp, warp-reduce only) ----
    {
        #pragma unroll
        for (int r = 0; r < 2; ++r) {
            const int row = m_base + n_tile * 8 + wid * 2 + r;
            const float* xr = x + (size_t)row * IN_DIM;
            float s = 0.0f;
            float4 v[16];
            #pragma unroll
            for (int i = 0; i < 16; ++i) {
                v[i] = *reinterpret_cast<const float4*>(xr + lane * 4 + i * 128);
                s += v[i].x * v[i].x + v[i].y * v[i].y
                   + v[i].z * v[i].z + v[i].w * v[i].w;
            }
            #pragma unroll
            for (int off = 16; off; off >>= 1)
                s += __shfl_xor_sync(0xffffffffu, s, off);
            const float inv = 1.0f / (sqrtf(s) + 1e-4f);
            __half* dst = g_x16 + (size_t)row * IN_DIM;
            #pragma unroll
            for (int i = 0; i < 16; ++i) {
                __half2 h[2];
                h[0] = __floats2half2_rn(v[i].x * inv, v[i].y * inv);
                h[1] = __floats2half2_rn(v[i].z * inv, v[i].w * inv);
                *reinterpret_cast<uint2*>(dst + lane * 4 + i * 128) =
                    *reinterpret_cast<uint2*>(h);
            }
        }
        __syncthreads();
        if (tid == 0) {
            __threadfence();
            atomicAdd(&g_cnt[m_tile], 1);
            // ---- wait for all 16 producers of this m_tile ----
            while (atomicAdd(&g_cnt[m_tile], 0) < 16) { }
        }
        __syncthreads();
    }

    // ---- Phase 1: R2 GEMM core (unchanged) ----
    const __half* Ag = g_x16 + (size_t)m_base * IN_DIM;
    const __half* Bg = g_w16 + (size_t)n_base * IN_DIM;

    float c[4][8][4];
    #pragma unroll
    for (int mt = 0; mt < 4; ++mt)
        #pragma unroll
        for (int nt = 0; nt < 8; ++nt)
            #pragma unroll
            for (int i = 0; i < 4; ++i) c[mt][nt][i] = 0.0f;

    // fill: 4 A rows + 4 B rows per thread, static strides
    const uint32_t smF = (uint32_t)((tid >> 2) * ROW_STRIDE + (tid & 3) * 16);
    const size_t gF = (size_t)(tid >> 2) * IN_DIM + (tid & 3) * 8;
    auto fill = [&](int slot, int kk) {
        const uint32_t a_s = smem_base + SMEM_A + slot * A_STAGE_BYTES + smF;
        const uint32_t b_s = smem_base + SMEM_B + slot * B_STAGE_BYTES + smF;
        const __half* Af = Ag + gF + kk;
        const __half* Bf = Bg + gF + kk;
        #pragma unroll
        for (int j = 0; j < 4; ++j)
            cp16(a_s + j * (32 * ROW_STRIDE), Af + (size_t)j * (32 * IN_DIM));
        #pragma unroll
        for (int j = 0; j < 4; ++j)
            cp16(b_s + j * (32 * ROW_STRIDE), Bf + (size_t)j * (32 * IN_DIM));
    };

    // Prologue: fill 3 of 4 slots
    #pragma unroll
    for (int s = 0; s < STAGES - 1; ++s) {
        fill(s, s * KC);
        asm volatile("cp.async.commit_group;" ::: "memory");
    }

    // ldmatrix per-thread offsets
    const uint32_t a_thread_off =
        (uint32_t)((warp_m * 64 + (lane & 15)) * ROW_STRIDE + ((lane >> 4) << 4));
    const uint32_t b_thread_off =
        (uint32_t)((warp_n * 64 + ((lane >> 4) << 3) + (lane & 7)) * ROW_STRIDE
                   + ((lane & 8) << 1));

    for (int k = 0; k < KSTEPS; ++k) {
        const int slot = k & (STAGES - 1);
        asm volatile("cp.async.wait_group %0;" :: "n"(STAGES - 2) : "memory");
        __syncthreads();

        // prefetch stage k+3 into its slot (consumed in iter k-1)
        if (k + STAGES - 1 < KSTEPS)
            fill((k + STAGES - 1) & (STAGES - 1), (k + STAGES - 1) * KC);
        asm volatile("cp.async.commit_group;" ::: "memory");

        const uint32_t a_base = smem_base + SMEM_A + slot * A_STAGE_BYTES + a_thread_off;
        const uint32_t b_base = smem_base + SMEM_B + slot * B_STAGE_BYTES + b_thread_off;

        #pragma unroll
        for (int s = 0; s < 2; ++s) {           // two k16 steps per KC=32
            uint32_t a[4][4];
            uint32_t b[4][4];
            #pragma unroll
            for (int mt = 0; mt < 4; ++mt)
                ldsm_x4(a[mt], a_base + mt * (16 * ROW_STRIDE) + s * 32);
            #pragma unroll
            for (int nt2 = 0; nt2 < 4; ++nt2)
                ldsm_x4(b[nt2], b_base + nt2 * (16 * ROW_STRIDE) + s * 32);
            #pragma unroll
            for (int mt = 0; mt < 4; ++mt)
                #pragma unroll
                for (int nt = 0; nt < 8; ++nt)
                    mma16816(c[mt][nt], a[mt], &b[nt >> 1][(nt & 1) * 2]);
        }
    }

    // Epilogue: bias + ReLU, fp32 stores (8B pairs)
    const int row0 = m_base + warp_m * 64 + (lane >> 2);
    const int col0 = n_base + warp_n * 64 + 2 * (lane & 3);
    float2 bv[8];
    #pragma unroll
    for (int nt = 0; nt < 8; ++nt)
        bv[nt] = *reinterpret_cast<const float2*>(&bias[col0 + nt * 8]);

    #pragma unroll
    for (int mt = 0; mt < 4; ++mt) {
        const size_t r0 = (size_t)(row0 + mt * 16) * OUT_DIM;
        const size_t r1 = r0 + 8 * OUT_DIM;
        #pragma unroll
        for (int nt = 0; nt < 8; ++nt) {
            const int cc = col0 + nt * 8;
            float2 v0, v1;
            v0.x = fmaxf(c[mt][nt][0] + bv[nt].x, 0.0f);
            v0.y = fmaxf(c[mt][nt][1] + bv[nt].y, 0.0f);
            v1.x = fmaxf(c[mt][nt][2] + bv[nt].x, 0.0f);
            v1.y = fmaxf(c[mt][nt][3] + bv[nt].y, 0.0f);
            *reinterpret_cast<float2*>(out + r0 + cc) = v0;
            *reinterpret_cast<float2*>(out + r1 + cc) = v1;
        }
    }
}

// ---------------------------------------------------------------------------
// Launch
// ---------------------------------------------------------------------------
extern "C" void kernel_launch(void* const* d_in, const int* in_sizes, int n_in,
                              void* d_out, int out_size) {
    const float* x = (const float*)d_in[0];
    const float* W = (const float*)d_in[1];
    const float* b = (const float*)d_in[2];
    float* out = (float*)d_out;

    cudaFuncSetAttribute(gemm_kernel, cudaFuncAttributeMaxDynamicSharedMemorySize,
                         SMEM_TOTAL);

    prep_w_kernel<<<(OUT_DIM * IN_DIM) / (256 * 8), 256>>>(W);

    dim3 grid(OUT_DIM / TN, B_ROWS / TM);   // (16, 128), n-tile fastest
    gemm_kernel<<<grid, 128, SMEM_TOTAL>>>(x, b, out);
}